// round 4
// baseline (speedup 1.0000x reference)
#include <cuda_runtime.h>
#include <cstdint>
#include <cstddef>

#define T_SEQ 2048
#define H_DIM 256
#define I_DIM 1739
#define G3    768   // 3*H
#define NCTA  8     // cluster size

// ---------------- device scratch (no allocation allowed) ----------------
__device__ float g_xp_enc[T_SEQ * G3];
__device__ float g_xp_dec[T_SEQ * G3];
__device__ float g_h_enc[H_DIM];
__device__ float g_hs[T_SEQ * H_DIM];

// =======================================================================
// SGEMM "NT": C[M][N] = A[M][K] @ B[N][K]^T + bias[N]
// A row-major [M][K], B row-major [N][K] (PyTorch weight layout).
// 64x64 tile, BK=32, 256 threads, 4x4 microtile.
// =======================================================================
__global__ __launch_bounds__(256) void sgemm_nt(
    const float* __restrict__ A, const float* __restrict__ B,
    const float* __restrict__ bias, float* __restrict__ C,
    int M, int N, int K)
{
    __shared__ float As[64][33];
    __shared__ float Bs[64][33];

    const int bm = blockIdx.y * 64;
    const int bn = blockIdx.x * 64;
    const int tid = threadIdx.x;
    const int tr = tid >> 4;   // 0..15
    const int tc = tid & 15;   // 0..15

    float acc[4][4];
#pragma unroll
    for (int i = 0; i < 4; i++)
#pragma unroll
        for (int j = 0; j < 4; j++) acc[i][j] = 0.f;

    for (int k0 = 0; k0 < K; k0 += 32) {
        // cooperative load: 64x32 tiles, coalesced (consecutive tid -> consecutive k)
#pragma unroll
        for (int i = 0; i < 8; i++) {
            int e   = i * 256 + tid;
            int r   = e >> 5;
            int cix = e & 31;
            int gk  = k0 + cix;
            As[r][cix] = (gk < K) ? A[(size_t)(bm + r) * K + gk] : 0.f;
            Bs[r][cix] = (gk < K && (bn + r) < N) ? B[(size_t)(bn + r) * K + gk] : 0.f;
        }
        __syncthreads();
#pragma unroll
        for (int kk = 0; kk < 32; kk++) {
            float a[4], b[4];
#pragma unroll
            for (int i = 0; i < 4; i++) a[i] = As[tr * 4 + i][kk];
#pragma unroll
            for (int j = 0; j < 4; j++) b[j] = Bs[tc * 4 + j][kk];
#pragma unroll
            for (int i = 0; i < 4; i++)
#pragma unroll
                for (int j = 0; j < 4; j++)
                    acc[i][j] = fmaf(a[i], b[j], acc[i][j]);
        }
        __syncthreads();
    }

#pragma unroll
    for (int i = 0; i < 4; i++) {
        int gm = bm + tr * 4 + i;
#pragma unroll
        for (int j = 0; j < 4; j++) {
            int gn = bn + tc * 4 + j;
            if (gn < N)
                C[(size_t)gm * N + gn] = acc[i][j] + bias[gn];
        }
    }
}

// =======================================================================
// GRU recurrence: one 8-CTA cluster, W_hh in registers.
//
// Output partition: CTA c owns h-indices gi in [c*32, c*32+32) and the three
// W_hh rows {gi, H+gi, 2H+gi} -> 96 matvec outputs per CTA.
// 384 threads = 12 warps; warp w computes local outputs w*8 .. w*8+7; within
// a warp, lane l works on output (l>>2) with K-slice kg = l&3.
// K interleave: lane kg covers float4 chunks {i*4+kg : i=0..15} so the h
// LDS.128 of a warp touches 4 distinct consecutive float4 (64B) -> conflict-
// free broadcast. W values preloaded into 16 float4 registers per thread.
//
// h is double-buffered in SMEM; the 32 gate threads broadcast h_new to all
// 8 CTAs via mapa + st.shared::cluster, then one barrier.cluster per step
// (arrive=release / wait=acquire orders the remote stores).
// =======================================================================
__global__ void __cluster_dims__(NCTA, 1, 1) __launch_bounds__(384, 1)
gru_rec(const float* __restrict__ xp,      // [T][3H], b_ih already folded in
        const float* __restrict__ W_hh,    // [3H][H]
        const float* __restrict__ b_hh,    // [3H]
        const float* __restrict__ h0,      // [H] or nullptr (-> zeros)
        float* __restrict__ h_final,       // [H] or nullptr
        float* __restrict__ hs_out)        // [T][H] or nullptr
{
    __shared__ float hbuf[2][H_DIM];
    __shared__ float hh_s[96];

    const int c    = blockIdx.x;          // == cluster rank (grid = 1 cluster)
    const int tid  = threadIdx.x;
    const int w    = tid >> 5;
    const int lane = tid & 31;
    const int lout = (w << 3) + (lane >> 2);   // 0..95
    const int kg   = lane & 3;                 // K-slice
    const int gate = lout >> 5;                // 0..2
    const int ii   = lout & 31;
    const int row  = (gate << 8) + (c << 5) + ii;   // W_hh row, 0..767

    // preload W slice: 64 floats as 16 float4 in registers
    float4 wv[16];
    const float4* Wr = reinterpret_cast<const float4*>(W_hh) + (size_t)row * 64;
#pragma unroll
    for (int i = 0; i < 16; i++) wv[i] = Wr[i * 4 + kg];

    // gate-thread constants
    const int gi_g = (c << 5) + tid;  // valid when tid < 32
    float bhr = 0.f, bhz = 0.f, bhn = 0.f;
    if (tid < 32) {
        bhr = b_hh[gi_g];
        bhz = b_hh[H_DIM + gi_g];
        bhn = b_hh[2 * H_DIM + gi_g];
    }

    if (tid < H_DIM) hbuf[0][tid] = h0 ? h0[tid] : 0.f;
    __syncthreads();

    int cur = 0;
    for (int t = 0; t < T_SEQ; t++) {
        // prefetch x-projection for this step (long slack before use)
        float xr = 0.f, xz = 0.f, xn = 0.f;
        if (tid < 32) {
            const float* xpt = xp + (size_t)t * G3 + gi_g;
            xr = __ldg(xpt);
            xz = __ldg(xpt + H_DIM);
            xn = __ldg(xpt + 2 * H_DIM);
        }

        // matvec partial: 64 MACs per lane, W in regs, h from SMEM
        const float4* h4 = reinterpret_cast<const float4*>(&hbuf[cur][0]);
        float a0 = 0.f, a1 = 0.f, a2 = 0.f, a3 = 0.f;
#pragma unroll
        for (int i = 0; i < 16; i++) {
            float4 hv = h4[i * 4 + kg];
            a0 = fmaf(wv[i].x, hv.x, a0);
            a1 = fmaf(wv[i].y, hv.y, a1);
            a2 = fmaf(wv[i].z, hv.z, a2);
            a3 = fmaf(wv[i].w, hv.w, a3);
        }
        float acc = (a0 + a1) + (a2 + a3);
        acc += __shfl_xor_sync(0xffffffffu, acc, 1);
        acc += __shfl_xor_sync(0xffffffffu, acc, 2);
        if (kg == 0) hh_s[lout] = acc;
        __syncthreads();

        if (tid < 32) {
            float hr = hh_s[tid]      + bhr;
            float hz = hh_s[32 + tid] + bhz;
            float hn = hh_s[64 + tid] + bhn;
            float hprev = hbuf[cur][gi_g];

            float r = 1.f / (1.f + __expf(-(xr + hr)));
            float z = 1.f / (1.f + __expf(-(xz + hz)));
            float pre = xn + r * hn;
            pre = fminf(fmaxf(pre, -20.f), 20.f);
            float e2 = __expf(-2.f * pre);
            float n  = (1.f - e2) / (1.f + e2);          // tanh
            float hnew = (1.f - z) * n + z * hprev;

            if (hs_out)  hs_out[(size_t)t * H_DIM + gi_g] = hnew;
            if (h_final && t == T_SEQ - 1) h_final[gi_g] = hnew;

            // broadcast h_new[gi] into every CTA's next buffer
            uint32_t dst_local =
                (uint32_t)__cvta_generic_to_shared(&hbuf[cur ^ 1][gi_g]);
#pragma unroll
            for (int rk = 0; rk < NCTA; rk++) {
                uint32_t rem;
                asm volatile("mapa.shared::cluster.u32 %0, %1, %2;"
                             : "=r"(rem) : "r"(dst_local), "r"(rk));
                asm volatile("st.shared::cluster.f32 [%0], %1;"
                             :: "r"(rem), "f"(hnew) : "memory");
            }
        }

        // one cluster barrier per step: release remote stores, acquire peers'
        asm volatile("barrier.cluster.arrive.aligned;" ::: "memory");
        asm volatile("barrier.cluster.wait.aligned;"   ::: "memory");
        cur ^= 1;
    }
}

// =======================================================================
// launch
// =======================================================================
extern "C" void kernel_launch(void* const* d_in, const int* in_sizes, int n_in,
                              void* d_out, int out_size)
{
    const float* x        = (const float*)d_in[0];   // [1,T,I]
    const float* W_ih_enc = (const float*)d_in[2];   // [3H,I]
    const float* W_hh_enc = (const float*)d_in[3];   // [3H,H]
    const float* b_ih_enc = (const float*)d_in[4];
    const float* b_hh_enc = (const float*)d_in[5];
    const float* W_ih_dec = (const float*)d_in[6];
    const float* W_hh_dec = (const float*)d_in[7];
    const float* b_ih_dec = (const float*)d_in[8];
    const float* b_hh_dec = (const float*)d_in[9];
    const float* W_out    = (const float*)d_in[10];  // [I,H]
    const float* b_out    = (const float*)d_in[11];
    float* out = (float*)d_out;                      // [T,1,I]

    float *xpe, *xpd, *henc, *hs;
    cudaGetSymbolAddress((void**)&xpe,  g_xp_enc);
    cudaGetSymbolAddress((void**)&xpd,  g_xp_dec);
    cudaGetSymbolAddress((void**)&henc, g_h_enc);
    cudaGetSymbolAddress((void**)&hs,   g_hs);

    // x_proj = x @ W_ih^T + b_ih  (both GRUs)
    dim3 gXP((G3 + 63) / 64, T_SEQ / 64);
    sgemm_nt<<<gXP, 256>>>(x, W_ih_enc, b_ih_enc, xpe, T_SEQ, G3, I_DIM);
    sgemm_nt<<<gXP, 256>>>(x, W_ih_dec, b_ih_dec, xpd, T_SEQ, G3, I_DIM);

    // encoder recurrence (h0 = 0, keep only h_T)
    gru_rec<<<NCTA, 384>>>(xpe, W_hh_enc, b_hh_enc, nullptr, henc, nullptr);
    // decoder recurrence (h0 = h_enc, keep all hs)
    gru_rec<<<NCTA, 384>>>(xpd, W_hh_dec, b_hh_dec, henc, nullptr, hs);

    // preds = hs @ W_out^T + b_out
    dim3 gO((I_DIM + 63) / 64, T_SEQ / 64);
    sgemm_nt<<<gO, 256>>>(hs, W_out, b_out, out, T_SEQ, I_DIM, H_DIM);
}